// round 6
// baseline (speedup 1.0000x reference)
#include <cuda_runtime.h>

// Soft 5x5 dilation:  y = logsumexp((w + patch)*B)/B
// Factored:  y = log2( conv5x5( exp2(c*x), exp2(c*w) ) ) * (ln2/B),  c = B*log2e
// Zero-pad of x -> pad value 1.0 in exp-space.
// Packed fma.rn.f32x2 conv; 2 tiles per block -> single wave on 148 SMs.

#define KK 5
#define BETA 15.0f
#define CC 64
#define HH 128
#define WW 128
#define BB 4

#define TILE_H 16
#define SROWS (TILE_H + 4)      // 20
#define SCOLS 132               // smem col = input col + 2
#define NT 128

#define B_LOG2E (BETA * 1.44269504f)
#define LN2_OVER_B (0.69314718f / BETA)

__device__ __forceinline__ float fast_ex2(float v) {
    float r; asm("ex2.approx.ftz.f32 %0, %1;" : "=f"(r) : "f"(v)); return r;
}
__device__ __forceinline__ float fast_lg2(float v) {
    float r; asm("lg2.approx.ftz.f32 %0, %1;" : "=f"(r) : "f"(v)); return r;
}

union F2U { float2 f; unsigned long long u; };
__device__ __forceinline__ float2 ffma2(float2 a, float2 b, float2 c) {
    F2U A, B, C, D; A.f = a; B.f = b; C.f = c;
    asm("fma.rn.f32x2 %0, %1, %2, %3;" : "=l"(D.u) : "l"(A.u), "l"(B.u), "l"(C.u));
    return D.f;
}

__global__ __launch_bounds__(NT, 8)
void morph_soft_dilate_kernel(const float* __restrict__ x,
                              const float* __restrict__ wy,
                              float* __restrict__ out)
{
    __shared__ float sE[SROWS][SCOLS];   // 10560 B
    __shared__ float sA[32];

    const int img   = blockIdx.y;          // b*C + c
    const int c     = img & (CC - 1);
    const int t     = threadIdx.x;
    const int lane  = t & 31;
    const int r0    = t >> 5;

    const float* xi = x + (size_t)img * (HH * WW);
    float*       oi = out + (size_t)img * (HH * WW);

    // one-time setup: taps in exp space; halo cols (never overwritten by loaders)
    if (t < KK * KK)
        sA[t] = fast_ex2(B_LOG2E * wy[c * KK * KK + t]);
    if (t < 40) {
        int r  = t >> 1;
        int cb = (t & 1) ? 130 : 0;
        sE[r][cb]     = 1.0f;
        sE[r][cb + 1] = 1.0f;
    }

    #pragma unroll
    for (int tt = 0; tt < 2; tt++) {
        const int tileY = blockIdx.x * (2 * TILE_H) + tt * TILE_H;

        // pad rows at true image edges only (before the tile's sync)
        {
            float4* sp = (float4*)&sE[0][0];
            const float4 ones = make_float4(1.f, 1.f, 1.f, 1.f);
            if (tileY == 0 && t < 66)              sp[t] = ones;        // rows 0,1
            if (tileY == HH - TILE_H && t < 66)    sp[594 + t] = ones;  // rows 18,19
        }

        // hoisted predicated LDG batch (MLP=5)
        float4 v[5];
        bool ok[5];
        #pragma unroll
        for (int p = 0; p < 5; p++) {
            int gr = tileY + r0 + 4 * p - 2;
            ok[p] = (gr >= 0) && (gr < HH);
            if (ok[p]) v[p] = *(const float4*)&xi[gr * WW + 4 * lane];
        }
        // convert + STS
        #pragma unroll
        for (int p = 0; p < 5; p++) {
            if (ok[p]) {
                int r = r0 + 4 * p;
                float2 e01 = make_float2(fast_ex2(B_LOG2E * v[p].x), fast_ex2(B_LOG2E * v[p].y));
                float2 e23 = make_float2(fast_ex2(B_LOG2E * v[p].z), fast_ex2(B_LOG2E * v[p].w));
                *(float2*)&sE[r][4 * lane + 2] = e01;
                *(float2*)&sE[r][4 * lane + 4] = e23;
            }
        }
        __syncthreads();

        // taps duplicated into both f32x2 lanes (warp-broadcast LDS)
        float2 a2[KK * KK];
        #pragma unroll
        for (int i = 0; i < KK * KK; i++) { float w0 = sA[i]; a2[i] = make_float2(w0, w0); }

        const int cg = lane;
        const int sy = r0 * 4;

        float2 acc01[4], acc23[4];
        #pragma unroll
        for (int q = 0; q < 4; q++) {
            acc01[q] = make_float2(0.f, 0.f);
            acc23[q] = make_float2(0.f, 0.f);
        }

        #pragma unroll
        for (int rr = 0; rr < 8; rr++) {
            float4 q0 = *(const float4*)&sE[sy + rr][4 * cg];
            float4 q1 = *(const float4*)&sE[sy + rr][4 * cg + 4];
            float2 p[7];
            p[0] = make_float2(q0.x, q0.y);
            p[1] = make_float2(q0.y, q0.z);
            p[2] = make_float2(q0.z, q0.w);
            p[3] = make_float2(q0.w, q1.x);
            p[4] = make_float2(q1.x, q1.y);
            p[5] = make_float2(q1.y, q1.z);
            p[6] = make_float2(q1.z, q1.w);
            #pragma unroll
            for (int ky = 0; ky < KK; ky++) {
                int vo = rr - ky;
                if (vo >= 0 && vo < 4) {
                    #pragma unroll
                    for (int kx = 0; kx < KK; kx++) {
                        acc01[vo] = ffma2(a2[ky * KK + kx], p[kx],     acc01[vo]);
                        acc23[vo] = ffma2(a2[ky * KK + kx], p[kx + 2], acc23[vo]);
                    }
                }
            }
        }

        #pragma unroll
        for (int q = 0; q < 4; q++) {
            float4 o;
            o.x = fast_lg2(acc01[q].x) * LN2_OVER_B;
            o.y = fast_lg2(acc01[q].y) * LN2_OVER_B;
            o.z = fast_lg2(acc23[q].x) * LN2_OVER_B;
            o.w = fast_lg2(acc23[q].y) * LN2_OVER_B;
            *(float4*)&oi[(tileY + sy + q) * WW + 4 * cg] = o;
        }

        // smem buffer reused by next tile: all reads must finish first
        if (tt == 0) __syncthreads();
    }
}

extern "C" void kernel_launch(void* const* d_in, const int* in_sizes, int n_in,
                              void* d_out, int out_size)
{
    const float* x  = (const float*)d_in[0];   // (4, 64, 128, 128) fp32
    const float* wy = (const float*)d_in[1];   // (64, 5, 5) fp32
    float* out = (float*)d_out;                // (4, 64, 128, 128) fp32

    dim3 grid(HH / (2 * TILE_H), BB * CC);     // (4, 256) = 1024 blocks, single wave
    morph_soft_dilate_kernel<<<grid, NT>>>(x, wy, out);
}

// round 7
// speedup vs baseline: 1.0201x; 1.0201x over previous
#include <cuda_runtime.h>

// Soft 5x5 dilation:  y = logsumexp((w + patch)*B)/B
// Factored:  y = log2( conv5x5( exp2(c*x), exp2(c*w) ) ) * (ln2/B),  c = B*log2e
// Zero-pad of x -> pad value 1.0 in exp-space.
// Conv: packed fma.rn.f32x2 with u64-carried register pairs end-to-end.

#define KK 5
#define BETA 15.0f
#define CC 64
#define HH 128
#define WW 128
#define BB 4

#define TILE_H 16
#define SROWS (TILE_H + 4)      // 20
#define SCOLS 132               // smem col = input col + 2
#define NT 128

#define B_LOG2E (BETA * 1.44269504f)
#define LN2_OVER_B (0.69314718f / BETA)

typedef unsigned long long u64;

__device__ __forceinline__ float fast_ex2(float v) {
    float r; asm("ex2.approx.ftz.f32 %0, %1;" : "=f"(r) : "f"(v)); return r;
}
__device__ __forceinline__ float fast_lg2(float v) {
    float r; asm("lg2.approx.ftz.f32 %0, %1;" : "=f"(r) : "f"(v)); return r;
}
// pack two floats into an aligned register pair (u64 carrier)
__device__ __forceinline__ u64 pack2(float lo, float hi) {
    u64 r; asm("mov.b64 %0, {%1, %2};" : "=l"(r) : "f"(lo), "f"(hi)); return r;
}
__device__ __forceinline__ void unpack2(u64 v, float& lo, float& hi) {
    asm("mov.b64 {%0, %1}, %2;" : "=f"(lo), "=f"(hi) : "l"(v));
}
// d = a*b + c on packed f32x2, all operands stay u64
__device__ __forceinline__ u64 ffma2(u64 a, u64 b, u64 c) {
    u64 d; asm("fma.rn.f32x2 %0, %1, %2, %3;" : "=l"(d) : "l"(a), "l"(b), "l"(c)); return d;
}

__global__ __launch_bounds__(NT, 8)
void morph_soft_dilate_kernel(const float* __restrict__ x,
                              const float* __restrict__ wy,
                              float* __restrict__ out)
{
    __shared__ float sE[SROWS][SCOLS];   // 10560 B
    __shared__ float sA[32];

    const int img   = blockIdx.y;          // b*C + c
    const int c     = img & (CC - 1);
    const int tileY = blockIdx.x * TILE_H;
    const int t     = threadIdx.x;
    const int lane  = t & 31;
    const int r0    = t >> 5;

    const float* xi = x + (size_t)img * (HH * WW);

    // hoisted predicated LDG batch (MLP=5)
    float4 v[5];
    bool ok[5];
    #pragma unroll
    for (int p = 0; p < 5; p++) {
        int gr = tileY + r0 + 4 * p - 2;
        ok[p] = (gr >= 0) && (gr < HH);
        if (ok[p]) v[p] = *(const float4*)&xi[gr * WW + 4 * lane];
    }

    // setup overlapping LDG latency
    if (t < KK * KK)
        sA[t] = fast_ex2(B_LOG2E * wy[c * KK * KK + t]);
    if (t < 40) {                       // halo cols 0,1,130,131 all 20 rows
        int r  = t >> 1;
        int cb = (t & 1) ? 130 : 0;
        sE[r][cb]     = 1.0f;
        sE[r][cb + 1] = 1.0f;
    }
    {                                   // pad rows at true image edges only
        float4* sp = (float4*)&sE[0][0];
        const float4 ones = make_float4(1.f, 1.f, 1.f, 1.f);
        if (tileY == 0 && t < 66)              sp[t] = ones;        // rows 0,1
        if (tileY == HH - TILE_H && t < 66)    sp[594 + t] = ones;  // rows 18,19
    }

    // convert + STS (packed 8B stores, 8B-aligned: col 4*lane+2)
    #pragma unroll
    for (int p = 0; p < 5; p++) {
        if (ok[p]) {
            int r = r0 + 4 * p;
            u64 e01 = pack2(fast_ex2(B_LOG2E * v[p].x), fast_ex2(B_LOG2E * v[p].y));
            u64 e23 = pack2(fast_ex2(B_LOG2E * v[p].z), fast_ex2(B_LOG2E * v[p].w));
            *(u64*)&sE[r][4 * lane + 2] = e01;
            *(u64*)&sE[r][4 * lane + 4] = e23;
        }
    }
    __syncthreads();

    // taps duplicated into both f32x2 lanes, packed once
    u64 a2[KK * KK];
    #pragma unroll
    for (int i = 0; i < KK * KK; i++) { float w0 = sA[i]; a2[i] = pack2(w0, w0); }

    const int cg = lane;            // output cols 4*cg .. 4*cg+3
    const int sy = r0 * 4;          // output rows tileY+sy .. +3

    u64 acc01[4], acc23[4];
    #pragma unroll
    for (int q = 0; q < 4; q++) { acc01[q] = 0ull; acc23[q] = 0ull; }  // 0x0 = {0.f,0.f}

    // 8 smem rows feed the 4x4 patch; per row: 2x LDS.128 -> 4 aligned u64 pairs,
    // 3 odd pairs built, then packed FFMA2 chains.
    #pragma unroll
    for (int rr = 0; rr < 8; rr++) {
        ulonglong2 w0 = *(const ulonglong2*)&sE[sy + rr][4 * cg];      // P0=(f0,f1) P1=(f2,f3)
        ulonglong2 w1 = *(const ulonglong2*)&sE[sy + rr][4 * cg + 4];  // P2=(f4,f5) P3=(f6,f7)
        u64 p[7];
        p[0] = w0.x;
        p[2] = w0.y;
        p[4] = w1.x;
        p[6] = w1.y;
        p[1] = (w0.x >> 32) | (w0.y << 32);   // (f1,f2)
        p[3] = (w0.y >> 32) | (w1.x << 32);   // (f3,f4)
        p[5] = (w1.x >> 32) | (w1.y << 32);   // (f5,f6)
        #pragma unroll
        for (int ky = 0; ky < KK; ky++) {
            int vo = rr - ky;
            if (vo >= 0 && vo < 4) {
                #pragma unroll
                for (int kx = 0; kx < KK; kx++) {
                    acc01[vo] = ffma2(a2[ky * KK + kx], p[kx],     acc01[vo]);
                    acc23[vo] = ffma2(a2[ky * KK + kx], p[kx + 2], acc23[vo]);
                }
            }
        }
    }

    float* oi = out + (size_t)img * (HH * WW);
    #pragma unroll
    for (int q = 0; q < 4; q++) {
        float s0, s1, s2, s3;
        unpack2(acc01[q], s0, s1);
        unpack2(acc23[q], s2, s3);
        float4 o;
        o.x = fast_lg2(s0) * LN2_OVER_B;
        o.y = fast_lg2(s1) * LN2_OVER_B;
        o.z = fast_lg2(s2) * LN2_OVER_B;
        o.w = fast_lg2(s3) * LN2_OVER_B;
        *(float4*)&oi[(tileY + sy + q) * WW + 4 * cg] = o;
    }
}

extern "C" void kernel_launch(void* const* d_in, const int* in_sizes, int n_in,
                              void* d_out, int out_size)
{
    const float* x  = (const float*)d_in[0];   // (4, 64, 128, 128) fp32
    const float* wy = (const float*)d_in[1];   // (64, 5, 5) fp32
    float* out = (float*)d_out;                // (4, 64, 128, 128) fp32

    dim3 grid(HH / TILE_H, BB * CC);           // (8, 256) = 2048 blocks
    morph_soft_dilate_kernel<<<grid, NT>>>(x, wy, out);
}